// round 1
// baseline (speedup 1.0000x reference)
#include <cuda_runtime.h>
#include <math.h>

// Problem constants
#define M_N     8192
#define IN_DIM  3000
#define HID     512
#define LAT     30
#define MAXD    192   // max neighbors per row (avg 33, binomial tail << 1e-50)

// ---------------- scratch (static device globals; no runtime alloc) ---------
__device__ float g_X[M_N * HID];     // projected features, 16 MB
__device__ float g_f0[M_N];
__device__ float g_f1[M_N];
__device__ int   g_idx[M_N * MAXD];  // per-row neighbor column indices
__device__ int   g_cnt[M_N];

// ---------------- Kernel 1: SGEMM X = A[8192,3000] @ W0[3000,512] -----------
// 128x128 tile, BK=8, 256 threads, 8x8 micro-tile per thread.
__global__ __launch_bounds__(256, 2)
void sgemm_kernel(const float* __restrict__ A, const float* __restrict__ B,
                  float* __restrict__ C)
{
    const int K = IN_DIM, N = HID;
    __shared__ float As[8][128];   // transposed A tile: As[k][m]
    __shared__ float Bs[8][128];

    const int bx = blockIdx.x;     // N block (0..3)
    const int by = blockIdx.y;     // M block (0..63)
    const int tid = threadIdx.x;

    const int tx = tid % 16;       // micro-tile col group
    const int ty = tid / 16;       // micro-tile row group

    // A tile loads: 128 rows x 8 cols = 1024 floats, 1 float4/thread
    const int a_row = tid >> 1;
    const int a_col = (tid & 1) * 4;
    // B tile loads: 8 rows x 128 cols, 1 float4/thread
    const int b_row = tid >> 5;
    const int b_col = (tid & 31) * 4;

    const float* Aptr = A + (size_t)(by * 128 + a_row) * K + a_col;
    const float* Bptr = B + (size_t)b_row * N + bx * 128 + b_col;

    float acc[8][8];
#pragma unroll
    for (int i = 0; i < 8; i++)
#pragma unroll
        for (int j = 0; j < 8; j++) acc[i][j] = 0.0f;

    for (int k0 = 0; k0 < K; k0 += 8) {
        float4 av = *(const float4*)(Aptr + k0);
        As[a_col + 0][a_row] = av.x;
        As[a_col + 1][a_row] = av.y;
        As[a_col + 2][a_row] = av.z;
        As[a_col + 3][a_row] = av.w;
        float4 bv = *(const float4*)(Bptr + (size_t)k0 * N);
        *(float4*)&Bs[b_row][b_col] = bv;
        __syncthreads();

#pragma unroll
        for (int kk = 0; kk < 8; kk++) {
            float ar[8], br[8];
#pragma unroll
            for (int i = 0; i < 8; i++) ar[i] = As[kk][ty * 8 + i];
#pragma unroll
            for (int j = 0; j < 8; j++) br[j] = Bs[kk][tx * 8 + j];
#pragma unroll
            for (int i = 0; i < 8; i++)
#pragma unroll
                for (int j = 0; j < 8; j++) acc[i][j] += ar[i] * br[j];
        }
        __syncthreads();
    }

    // write back
#pragma unroll
    for (int i = 0; i < 8; i++) {
        int row = by * 128 + ty * 8 + i;
        float* crow = C + (size_t)row * N + bx * 128 + tx * 8;
        float4 v0 = make_float4(acc[i][0], acc[i][1], acc[i][2], acc[i][3]);
        float4 v1 = make_float4(acc[i][4], acc[i][5], acc[i][6], acc[i][7]);
        *(float4*)(crow + 0) = v0;
        *(float4*)(crow + 4) = v1;
    }
}

// ---------------- Kernel 2: f0 = X@v0, f1 = X@v1 ----------------------------
__global__ void fvec_kernel(const float* __restrict__ X,
                            const float* __restrict__ v0,
                            const float* __restrict__ v1,
                            float* __restrict__ f0, float* __restrict__ f1)
{
    int warps_per_block = blockDim.x / 32;
    int row  = blockIdx.x * warps_per_block + threadIdx.x / 32;
    int lane = threadIdx.x & 31;
    if (row >= M_N) return;
    const float* xr = X + (size_t)row * HID;
    float s0 = 0.f, s1 = 0.f;
    for (int d = lane; d < HID; d += 32) {
        float x = xr[d];
        s0 += x * v0[d];
        s1 += x * v1[d];
    }
#pragma unroll
    for (int o = 16; o > 0; o >>= 1) {
        s0 += __shfl_xor_sync(0xffffffffu, s0, o);
        s1 += __shfl_xor_sync(0xffffffffu, s1, o);
    }
    if (lane == 0) { f0[row] = s0; f1[row] = s1; }
}

// ---------------- Kernel 3: sparsify graph rows ------------------------------
__global__ void sparsify_kernel(const float* __restrict__ graph,
                                int* __restrict__ idx, int* __restrict__ cnt)
{
    int row = blockIdx.x;
    __shared__ int c;
    if (threadIdx.x == 0) c = 0;
    __syncthreads();
    const float* g = graph + (size_t)row * M_N;
    for (int j = threadIdx.x; j < M_N; j += blockDim.x) {
        if (g[j] != 0.0f) {
            int s = atomicAdd(&c, 1);
            if (s < MAXD) idx[row * MAXD + s] = j;
        }
    }
    __syncthreads();
    if (threadIdx.x == 0) cnt[row] = (c < MAXD) ? c : MAXD;
}

// ---------------- Kernel 4: fused softmax-attn + agg + ELU + W1 -------------
__global__ __launch_bounds__(256)
void attn_kernel(const float* __restrict__ X,
                 const float* __restrict__ f0, const float* __restrict__ f1,
                 const float* __restrict__ W1,
                 const int* __restrict__ idx, const int* __restrict__ cnt,
                 float* __restrict__ out)
{
    const int row = blockIdx.x;
    const int t   = threadIdx.x;

    __shared__ int   s_idx[MAXD];
    __shared__ float s_alpha[MAXD];
    __shared__ float red[256];
    __shared__ float s_h[HID];
    __shared__ float s_part[8][32];

    const int n = cnt[row];      // >= 1 (self loop)
    for (int j = t; j < n; j += 256) s_idx[j] = idx[row * MAXD + j];
    __syncthreads();

    const float f0i = f0[row];

    // scores (n <= 192 < 256: one per thread)
    float my = 0.0f;
    float mx = -INFINITY;
    if (t < n) {
        float e   = f0i + f1[s_idx[t]];
        float sig = 1.0f / (1.0f + expf(-e));
        my = sig - 0.5f;
        mx = my;
    }
    // block-reduce max
    red[t] = mx;
    __syncthreads();
#pragma unroll
    for (int o = 128; o > 0; o >>= 1) {
        if (t < o) red[t] = fmaxf(red[t], red[t + o]);
        __syncthreads();
    }
    const float m = red[0];
    __syncthreads();

    // exp + block-reduce sum
    float e = 0.0f;
    if (t < n) e = expf(my - m);
    red[t] = e;
    __syncthreads();
#pragma unroll
    for (int o = 128; o > 0; o >>= 1) {
        if (t < o) red[t] += red[t + o];
        __syncthreads();
    }
    const float ssum = fmaxf(red[0], 1e-30f);
    if (t < n) s_alpha[t] = e / ssum;
    __syncthreads();

    // weighted aggregation: each thread owns h[t] and h[t+256]
    float acc0 = 0.0f, acc1 = 0.0f;
    for (int j = 0; j < n; j++) {
        const float a = s_alpha[j];
        const float* xr = X + (size_t)s_idx[j] * HID;
        acc0 += a * xr[t];
        acc1 += a * xr[t + 256];
    }
    // ELU
    acc0 = (acc0 > 0.0f) ? acc0 : expm1f(acc0);
    acc1 = (acc1 > 0.0f) ? acc1 : expm1f(acc1);
    s_h[t]       = acc0;
    s_h[t + 256] = acc1;
    __syncthreads();

    // W1 projection: 240 threads = 30 outputs x 8 slices of 64
    if (t < 240) {
        int k  = t % 30;
        int sl = t / 30;
        float p = 0.0f;
        const int d0 = sl * 64;
#pragma unroll 8
        for (int d = d0; d < d0 + 64; d++) p += s_h[d] * W1[d * LAT + k];
        s_part[sl][k] = p;
    }
    __syncthreads();
    if (t < LAT) {
        float r = 0.0f;
#pragma unroll
        for (int sl = 0; sl < 8; sl++) r += s_part[sl][t];
        out[(size_t)row * LAT + t] = r;
    }
}

// ---------------- launch ------------------------------------------------------
extern "C" void kernel_launch(void* const* d_in, const int* in_sizes, int n_in,
                              void* d_out, int out_size)
{
    const float* node_features = (const float*)d_in[0]; // [8192,3000]
    const float* graph         = (const float*)d_in[1]; // [8192,8192]
    const float* W0            = (const float*)d_in[2]; // [3000,512]
    const float* v0            = (const float*)d_in[3]; // [512]
    const float* v1            = (const float*)d_in[4]; // [512]
    const float* W1            = (const float*)d_in[5]; // [512,30]
    float* out = (float*)d_out;

    float *X, *f0, *f1;
    int *idx, *cnt;
    cudaGetSymbolAddress((void**)&X,   g_X);
    cudaGetSymbolAddress((void**)&f0,  g_f0);
    cudaGetSymbolAddress((void**)&f1,  g_f1);
    cudaGetSymbolAddress((void**)&idx, g_idx);
    cudaGetSymbolAddress((void**)&cnt, g_cnt);

    // 1) X = node_features @ W0
    dim3 ggrid(HID / 128, M_N / 128);
    sgemm_kernel<<<ggrid, 256>>>(node_features, W0, X);

    // 2) f0, f1
    fvec_kernel<<<M_N / 8, 256>>>(X, v0, v1, f0, f1);

    // 3) sparsify adjacency
    sparsify_kernel<<<M_N, 256>>>(graph, idx, cnt);

    // 4) fused attention + aggregation + ELU + W1
    attn_kernel<<<M_N, 256>>>(X, f0, f1, W1, idx, cnt, out);
}

// round 3
// speedup vs baseline: 1.9862x; 1.9862x over previous
#include <cuda_runtime.h>
#include <cuda_bf16.h>
#include <math.h>
#include <stdint.h>

// -------------------- problem constants --------------------
#define M_N     8192
#define IN_DIM  3000
#define K_PAD   3008        // 47 * 64
#define HID     512
#define LAT     30
#define MAXD    192

#define BM      128
#define BN      256
#define BK      64
#define NCHUNK  (K_PAD / BK)   // 47

// SMEM stage layout (bytes): Ah[128x64]=16K, Al=16K, Bh[256x64]=32K, Bl=32K
#define A_BYTES   16384
#define B_BYTES   32768
#define STAGE     (2 * A_BYTES + 2 * B_BYTES)    // 98304
#define SMEM_TOTAL (2 * STAGE)                   // 196608

// -------------------- static device scratch --------------------
__device__ __align__(16) float         g_X[(size_t)M_N * HID];        // 16 MB
__device__ float g_f0[M_N];
__device__ float g_f1[M_N];
__device__ int   g_idx[M_N * MAXD];
__device__ int   g_cnt[M_N];
__device__ __align__(16) __nv_bfloat16 g_Ahi[(size_t)M_N * K_PAD];
__device__ __align__(16) __nv_bfloat16 g_Alo[(size_t)M_N * K_PAD];
__device__ __align__(16) __nv_bfloat16 g_Bhi[(size_t)HID * K_PAD];    // [n][k]
__device__ __align__(16) __nv_bfloat16 g_Blo[(size_t)HID * K_PAD];

// -------------------- PTX helpers --------------------
__device__ __forceinline__ uint32_t smem_u32(const void* p) {
    uint32_t a;
    asm("{ .reg .u64 t; cvta.to.shared.u64 t, %1; cvt.u32.u64 %0, t; }"
        : "=r"(a) : "l"(p));
    return a;
}

__device__ __forceinline__ uint32_t sw128(uint32_t off) {
    return off ^ ((off >> 3) & 0x70);
}

__device__ __forceinline__ void cp_async16(uint32_t dst, const void* src) {
    asm volatile("cp.async.cg.shared.global [%0], [%1], 16;"
                 :: "r"(dst), "l"(src));
}
__device__ __forceinline__ void cp_commit() {
    asm volatile("cp.async.commit_group;" ::: "memory");
}

__device__ __forceinline__ void ldmx4(uint32_t* r, uint32_t addr) {
    asm volatile("ldmatrix.sync.aligned.m8n8.x4.shared.b16 {%0,%1,%2,%3}, [%4];"
                 : "=r"(r[0]), "=r"(r[1]), "=r"(r[2]), "=r"(r[3]) : "r"(addr));
}

__device__ __forceinline__ void mma_bf16(float* d, const uint32_t* a,
                                         const uint32_t* b) {
    asm volatile(
        "mma.sync.aligned.m16n8k16.row.col.f32.bf16.bf16.f32 "
        "{%0,%1,%2,%3}, {%4,%5,%6,%7}, {%8,%9}, {%0,%1,%2,%3};"
        : "+f"(d[0]), "+f"(d[1]), "+f"(d[2]), "+f"(d[3])
        : "r"(a[0]), "r"(a[1]), "r"(a[2]), "r"(a[3]), "r"(b[0]), "r"(b[1]));
}

// -------------------- Kernel 0a: split A into bf16 hi/lo --------------------
__global__ void convA_kernel(const float* __restrict__ A,
                             __nv_bfloat16* __restrict__ hi,
                             __nv_bfloat16* __restrict__ lo)
{
    int k   = blockIdx.x * 256 + threadIdx.x;
    int row = blockIdx.y;
    if (k >= K_PAD) return;
    float a = (k < IN_DIM) ? A[(size_t)row * IN_DIM + k] : 0.0f;
    __nv_bfloat16 h = __float2bfloat16(a);
    float r = a - __bfloat162float(h);
    hi[(size_t)row * K_PAD + k] = h;
    lo[(size_t)row * K_PAD + k] = __float2bfloat16(r);
}

// -------------------- Kernel 0b: transpose + split W0 -> [n][k] -------------
__global__ void convB_kernel(const float* __restrict__ W,
                             __nv_bfloat16* __restrict__ hi,
                             __nv_bfloat16* __restrict__ lo)
{
    __shared__ float tile[32][33];
    int k0 = blockIdx.x * 32;
    int n0 = blockIdx.y * 32;
    int tx = threadIdx.x, ty = threadIdx.y;   // block (32, 8)
#pragma unroll
    for (int r = 0; r < 4; r++) {
        int kk = ty + r * 8;
        int k  = k0 + kk;
        tile[kk][tx] = (k < IN_DIM) ? W[(size_t)k * HID + n0 + tx] : 0.0f;
    }
    __syncthreads();
#pragma unroll
    for (int r = 0; r < 4; r++) {
        int nn = ty + r * 8;
        float a = tile[tx][nn];
        __nv_bfloat16 h = __float2bfloat16(a);
        float res = a - __bfloat162float(h);
        size_t o = (size_t)(n0 + nn) * K_PAD + k0 + tx;
        hi[o] = h;
        lo[o] = __float2bfloat16(res);
    }
}

// -------------------- Kernel 1: bf16x3 warp-MMA GEMM ------------------------
// X[8192,512] = A[8192,3008] @ Bt[512,3008]^T  via  AhBh + AhBl + AlBh
__device__ __forceinline__ void load_chunk(uint32_t sb, int stage, int k0, int t,
                                           const __nv_bfloat16* Ah,
                                           const __nv_bfloat16* Al,
                                           const __nv_bfloat16* Bh,
                                           const __nv_bfloat16* Bl)
{
    uint32_t base = sb + stage * STAGE;
    // A tiles: 128 rows x 8 segs of 16B = 1024 uint4; 512 threads -> 2 each
#pragma unroll
    for (int i = 0; i < 2; i++) {
        int lin = t + i * 512;
        int row = lin >> 3, seg = lin & 7;
        uint32_t so = sw128(row * 128 + seg * 16);
        const __nv_bfloat16* ga = Ah + (size_t)row * K_PAD + k0 + seg * 8;
        const __nv_bfloat16* gl = Al + (size_t)row * K_PAD + k0 + seg * 8;
        cp_async16(base + so, ga);
        cp_async16(base + A_BYTES + so, gl);
    }
    // B tiles: 256 rows x 8 segs = 2048 uint4 -> 4 each
#pragma unroll
    for (int i = 0; i < 4; i++) {
        int lin = t + i * 512;
        int row = lin >> 3, seg = lin & 7;
        uint32_t so = sw128(row * 128 + seg * 16);
        const __nv_bfloat16* gb = Bh + (size_t)row * K_PAD + k0 + seg * 8;
        const __nv_bfloat16* gl = Bl + (size_t)row * K_PAD + k0 + seg * 8;
        cp_async16(base + 2 * A_BYTES + so, gb);
        cp_async16(base + 2 * A_BYTES + B_BYTES + so, gl);
    }
}

__global__ __launch_bounds__(512, 1)
void gemm_mma_kernel(float* __restrict__ Xout)
{
    extern __shared__ __align__(1024) char smem[];
    const uint32_t sb = smem_u32(smem);
    const int t    = threadIdx.x;
    const int wid  = t >> 5;
    const int lane = t & 31;
    const int wy   = wid >> 2;   // 0..3 : m group (32 rows)
    const int wx   = wid & 3;    // 0..3 : n group (64 cols)

    const __nv_bfloat16* Ah = g_Ahi + (size_t)(blockIdx.y * BM) * K_PAD;
    const __nv_bfloat16* Al = g_Alo + (size_t)(blockIdx.y * BM) * K_PAD;
    const __nv_bfloat16* Bh = g_Bhi + (size_t)(blockIdx.x * BN) * K_PAD;
    const __nv_bfloat16* Bl = g_Blo + (size_t)(blockIdx.x * BN) * K_PAD;

    float acc[2][8][4];
#pragma unroll
    for (int i = 0; i < 2; i++)
#pragma unroll
        for (int j = 0; j < 8; j++)
#pragma unroll
            for (int q = 0; q < 4; q++) acc[i][j][q] = 0.0f;

    // fragment smem address pre-computation (per-thread, swizzled)
    // A frag row/col within tile:
    const int a_row = (lane & 15);
    const int a_k8  = (lane >> 4);          // 0/1 -> +8 cols
    // B frag:
    const int b_row = ((lane >> 4) << 3) + (lane & 7);
    const int b_k8  = (lane >> 3) & 1;

    load_chunk(sb, 0, 0, t, Ah, Al, Bh, Bl);
    cp_commit();

    for (int c = 0; c < NCHUNK; c++) {
        if (c + 1 < NCHUNK) {
            load_chunk(sb, (c + 1) & 1, (c + 1) * BK, t, Ah, Al, Bh, Bl);
            cp_commit();
            asm volatile("cp.async.wait_group 1;" ::: "memory");
        } else {
            asm volatile("cp.async.wait_group 0;" ::: "memory");
        }
        __syncthreads();

        const uint32_t base = sb + (c & 1) * STAGE;
        const uint32_t aH = base;
        const uint32_t aL = base + A_BYTES;
        const uint32_t bH = base + 2 * A_BYTES;
        const uint32_t bL = base + 2 * A_BYTES + B_BYTES;

#pragma unroll
        for (int kk = 0; kk < 4; kk++) {
            uint32_t ah[2][4], al[2][4];
#pragma unroll
            for (int mt = 0; mt < 2; mt++) {
                int row = wy * 32 + mt * 16 + a_row;
                int kcol = kk * 16 + a_k8 * 8;
                uint32_t off = sw128(row * 128 + kcol * 2);
                ldmx4(ah[mt], aH + off);
                ldmx4(al[mt], aL + off);
            }
#pragma unroll
            for (int ng = 0; ng < 4; ng++) {
                int n = wx * 64 + ng * 16 + b_row;
                int kcol = kk * 16 + b_k8 * 8;
                uint32_t off = sw128(n * 128 + kcol * 2);
                uint32_t bh[4], bl[4];
                ldmx4(bh, bH + off);
                ldmx4(bl, bL + off);
#pragma unroll
                for (int mt = 0; mt < 2; mt++) {
                    mma_bf16(acc[mt][2 * ng],     ah[mt], bh);
                    mma_bf16(acc[mt][2 * ng + 1], ah[mt], bh + 2);
                    mma_bf16(acc[mt][2 * ng],     al[mt], bh);
                    mma_bf16(acc[mt][2 * ng + 1], al[mt], bh + 2);
                    mma_bf16(acc[mt][2 * ng],     ah[mt], bl);
                    mma_bf16(acc[mt][2 * ng + 1], ah[mt], bl + 2);
                }
            }
        }
        __syncthreads();
    }

    // epilogue: write fp32 C
    float* dst = Xout + (size_t)(blockIdx.y * BM + wy * 32) * HID
               + blockIdx.x * BN + wx * 64;
    const int r0 = lane >> 2;
    const int c0 = (lane & 3) * 2;
#pragma unroll
    for (int mt = 0; mt < 2; mt++) {
#pragma unroll
        for (int nt = 0; nt < 8; nt++) {
            float* p0 = dst + (size_t)(mt * 16 + r0) * HID + nt * 8 + c0;
            float* p1 = dst + (size_t)(mt * 16 + r0 + 8) * HID + nt * 8 + c0;
            *(float2*)p0 = make_float2(acc[mt][nt][0], acc[mt][nt][1]);
            *(float2*)p1 = make_float2(acc[mt][nt][2], acc[mt][nt][3]);
        }
    }
}

// -------------------- Kernel 2: f0 = X@v0, f1 = X@v1 ------------------------
__global__ void fvec_kernel(const float* __restrict__ X,
                            const float* __restrict__ v0,
                            const float* __restrict__ v1,
                            float* __restrict__ f0, float* __restrict__ f1)
{
    int row  = blockIdx.x * 8 + (threadIdx.x >> 5);
    int lane = threadIdx.x & 31;
    const float4* xr = (const float4*)(X + (size_t)row * HID);
    const float4* w0 = (const float4*)v0;
    const float4* w1 = (const float4*)v1;
    float s0 = 0.f, s1 = 0.f;
#pragma unroll
    for (int i = 0; i < 4; i++) {
        int d = lane + i * 32;
        float4 x = xr[d], a = w0[d], b = w1[d];
        s0 += x.x * a.x + x.y * a.y + x.z * a.z + x.w * a.w;
        s1 += x.x * b.x + x.y * b.y + x.z * b.z + x.w * b.w;
    }
#pragma unroll
    for (int o = 16; o > 0; o >>= 1) {
        s0 += __shfl_xor_sync(0xffffffffu, s0, o);
        s1 += __shfl_xor_sync(0xffffffffu, s1, o);
    }
    if (lane == 0) { f0[row] = s0; f1[row] = s1; }
}

// -------------------- Kernel 3: sparsify graph rows -------------------------
__global__ void sparsify_kernel(const float* __restrict__ graph,
                                int* __restrict__ idx, int* __restrict__ cnt)
{
    int row = blockIdx.x;
    __shared__ int c;
    if (threadIdx.x == 0) c = 0;
    __syncthreads();
    const float4* g = (const float4*)(graph + (size_t)row * M_N);
    for (int i = threadIdx.x; i < M_N / 4; i += 256) {
        float4 v = __ldg(&g[i]);
        if (v.x != 0.0f) { int s = atomicAdd(&c, 1); if (s < MAXD) idx[row * MAXD + s] = i * 4 + 0; }
        if (v.y != 0.0f) { int s = atomicAdd(&c, 1); if (s < MAXD) idx[row * MAXD + s] = i * 4 + 1; }
        if (v.z != 0.0f) { int s = atomicAdd(&c, 1); if (s < MAXD) idx[row * MAXD + s] = i * 4 + 2; }
        if (v.w != 0.0f) { int s = atomicAdd(&c, 1); if (s < MAXD) idx[row * MAXD + s] = i * 4 + 3; }
    }
    __syncthreads();
    if (threadIdx.x == 0) cnt[row] = (c < MAXD) ? c : MAXD;
}

// -------------------- Kernel 4: fused attention + agg + ELU + W1 ------------
__global__ __launch_bounds__(256)
void attn_kernel(const float* __restrict__ X,
                 const float* __restrict__ f0, const float* __restrict__ f1,
                 const float* __restrict__ W1,
                 const int* __restrict__ idx, const int* __restrict__ cnt,
                 float* __restrict__ out)
{
    const int row = blockIdx.x;
    const int t   = threadIdx.x;

    __shared__ int   s_idx[MAXD];
    __shared__ float s_alpha[MAXD];
    __shared__ float red[256];
    __shared__ float s_hq[4 * HID];
    __shared__ float s_h[HID];
    __shared__ float s_part[8][32];

    const int n = cnt[row];              // >= 1 (self loop)
    for (int j = t; j < n; j += 256) s_idx[j] = idx[row * MAXD + j];
    __syncthreads();

    const float f0i = f0[row];

    float my = 0.0f, mx = -INFINITY;
    if (t < n) {
        float e   = f0i + f1[s_idx[t]];
        float sig = 1.0f / (1.0f + expf(-e));
        my = sig - 0.5f;
        mx = my;
    }
    red[t] = mx;
    __syncthreads();
#pragma unroll
    for (int o = 128; o > 0; o >>= 1) {
        if (t < o) red[t] = fmaxf(red[t], red[t + o]);
        __syncthreads();
    }
    const float m = red[0];
    __syncthreads();

    float e = 0.0f;
    if (t < n) e = expf(my - m);
    red[t] = e;
    __syncthreads();
#pragma unroll
    for (int o = 128; o > 0; o >>= 1) {
        if (t < o) red[t] += red[t + o];
        __syncthreads();
    }
    const float ssum = fmaxf(red[0], 1e-30f);
    if (t < n) s_alpha[t] = e / ssum;
    __syncthreads();

    // aggregation: quarter q handles neighbors j ≡ q (mod 4)
    const int q = t >> 6;
    const int u = t & 63;
    float4 a0 = make_float4(0.f, 0.f, 0.f, 0.f);
    float4 a1 = make_float4(0.f, 0.f, 0.f, 0.f);
    for (int j = q; j < n; j += 4) {
        const float a = s_alpha[j];
        const float4* xr = (const float4*)(X + (size_t)s_idx[j] * HID);
        float4 x0 = xr[u * 2], x1 = xr[u * 2 + 1];
        a0.x += a * x0.x; a0.y += a * x0.y; a0.z += a * x0.z; a0.w += a * x0.w;
        a1.x += a * x1.x; a1.y += a * x1.y; a1.z += a * x1.z; a1.w += a * x1.w;
    }
    ((float4*)(s_hq + q * HID))[u * 2]     = a0;
    ((float4*)(s_hq + q * HID))[u * 2 + 1] = a1;
    __syncthreads();

    if (t < 128) {
        float4 r = make_float4(0.f, 0.f, 0.f, 0.f);
#pragma unroll
        for (int qq = 0; qq < 4; qq++) {
            float4 v = ((const float4*)s_hq)[qq * 128 + t];
            r.x += v.x; r.y += v.y; r.z += v.z; r.w += v.w;
        }
        r.x = (r.x > 0.f) ? r.x : expm1f(r.x);
        r.y = (r.y > 0.f) ? r.y : expm1f(r.y);
        r.z = (r.z > 0.f) ? r.z : expm1f(r.z);
        r.w = (r.w > 0.f) ? r.w : expm1f(r.w);
        ((float4*)s_h)[t] = r;
    }
    __syncthreads();

    if (t < 240) {
        int k  = t % 30;
        int sl = t / 30;
        float p = 0.0f;
        const int d0 = sl * 64;
#pragma unroll 8
        for (int d = d0; d < d0 + 64; d++) p += s_h[d] * W1[d * LAT + k];
        s_part[sl][k] = p;
    }
    __syncthreads();
    if (t < LAT) {
        float r = 0.0f;
#pragma unroll
        for (int sl = 0; sl < 8; sl++) r += s_part[sl][t];
        out[(size_t)row * LAT + t] = r;
    }
}

// -------------------- launch -------------------------------------------------
extern "C" void kernel_launch(void* const* d_in, const int* in_sizes, int n_in,
                              void* d_out, int out_size)
{
    const float* node_features = (const float*)d_in[0]; // [8192,3000]
    const float* graph         = (const float*)d_in[1]; // [8192,8192]
    const float* W0            = (const float*)d_in[2]; // [3000,512]
    const float* v0            = (const float*)d_in[3]; // [512]
    const float* v1            = (const float*)d_in[4]; // [512]
    const float* W1            = (const float*)d_in[5]; // [512,30]
    float* out = (float*)d_out;

    float *X, *f0, *f1;
    int *idx, *cnt;
    __nv_bfloat16 *Ahi, *Alo, *Bhi, *Blo;
    cudaGetSymbolAddress((void**)&X,   g_X);
    cudaGetSymbolAddress((void**)&f0,  g_f0);
    cudaGetSymbolAddress((void**)&f1,  g_f1);
    cudaGetSymbolAddress((void**)&idx, g_idx);
    cudaGetSymbolAddress((void**)&cnt, g_cnt);
    cudaGetSymbolAddress((void**)&Ahi, g_Ahi);
    cudaGetSymbolAddress((void**)&Alo, g_Alo);
    cudaGetSymbolAddress((void**)&Bhi, g_Bhi);
    cudaGetSymbolAddress((void**)&Blo, g_Blo);

    cudaFuncSetAttribute(gemm_mma_kernel,
                         cudaFuncAttributeMaxDynamicSharedMemorySize, SMEM_TOTAL);

    // 0) split-precision conversion
    convA_kernel<<<dim3(12, M_N), 256>>>(node_features, Ahi, Alo);
    convB_kernel<<<dim3(K_PAD / 32, HID / 32), dim3(32, 8)>>>(W0, Bhi, Blo);

    // 1) X = A @ W0 via bf16x3 warp MMA
    gemm_mma_kernel<<<dim3(HID / BN, M_N / BM), 512, SMEM_TOTAL>>>(X);

    // 2) f0, f1
    fvec_kernel<<<M_N / 8, 256>>>(X, v0, v1, f0, f1);

    // 3) sparsify adjacency
    sparsify_kernel<<<M_N, 256>>>(graph, idx, cnt);

    // 4) fused attention + aggregation + ELU + W1
    attn_kernel<<<M_N, 256>>>(X, f0, f1, W1, idx, cnt, out);
}

// round 4
// speedup vs baseline: 2.2966x; 1.1563x over previous
#include <cuda_runtime.h>
#include <cuda_bf16.h>
#include <math.h>
#include <stdint.h>

// -------------------- problem constants --------------------
#define M_N     8192
#define IN_DIM  3000
#define K_PAD   3008        // 47 * 64
#define HID     512
#define LAT     30
#define MAXD    192

#define BM      128
#define BN      256
#define BK      64
#define NCHUNK  (K_PAD / BK)   // 47

// SMEM stage layout (bytes): Ah[128x64]=16K, Al=16K, Bh[256x64]=32K, Bl=32K
#define A_BYTES   16384
#define B_BYTES   32768
#define STAGE     (2 * A_BYTES + 2 * B_BYTES)    // 98304
#define SMEM_TOTAL (2 * STAGE)                   // 196608

// -------------------- static device scratch --------------------
__device__ __align__(16) float         g_X[(size_t)M_N * HID];        // 16 MB
__device__ float g_f0[M_N];
__device__ float g_f1[M_N];
__device__ int   g_idx[M_N * MAXD];
__device__ int   g_cnt[M_N];
__device__ __align__(16) __nv_bfloat16 g_Bhi[(size_t)HID * K_PAD];    // [n][k]
__device__ __align__(16) __nv_bfloat16 g_Blo[(size_t)HID * K_PAD];

// -------------------- PTX helpers --------------------
__device__ __forceinline__ uint32_t smem_u32(const void* p) {
    uint32_t a;
    asm("{ .reg .u64 t; cvta.to.shared.u64 t, %1; cvt.u32.u64 %0, t; }"
        : "=r"(a) : "l"(p));
    return a;
}

__device__ __forceinline__ uint32_t sw128(uint32_t off) {
    return off ^ ((off >> 3) & 0x70);
}

__device__ __forceinline__ void cp_async16(uint32_t dst, const void* src) {
    asm volatile("cp.async.cg.shared.global [%0], [%1], 16;"
                 :: "r"(dst), "l"(src));
}
__device__ __forceinline__ void cp_commit() {
    asm volatile("cp.async.commit_group;" ::: "memory");
}

__device__ __forceinline__ void ldmx4(uint32_t* r, uint32_t addr) {
    asm volatile("ldmatrix.sync.aligned.m8n8.x4.shared.b16 {%0,%1,%2,%3}, [%4];"
                 : "=r"(r[0]), "=r"(r[1]), "=r"(r[2]), "=r"(r[3]) : "r"(addr));
}

__device__ __forceinline__ void mma_bf16(float* d, const uint32_t* a,
                                         const uint32_t* b) {
    asm volatile(
        "mma.sync.aligned.m16n8k16.row.col.f32.bf16.bf16.f32 "
        "{%0,%1,%2,%3}, {%4,%5,%6,%7}, {%8,%9}, {%0,%1,%2,%3};"
        : "+f"(d[0]), "+f"(d[1]), "+f"(d[2]), "+f"(d[3])
        : "r"(a[0]), "r"(a[1]), "r"(a[2]), "r"(a[3]), "r"(b[0]), "r"(b[1]));
}

// -------------------- Kernel 0: transpose + split W0 -> [n][k] --------------
__global__ void convB_kernel(const float* __restrict__ W,
                             __nv_bfloat16* __restrict__ hi,
                             __nv_bfloat16* __restrict__ lo)
{
    __shared__ float tile[32][33];
    int k0 = blockIdx.x * 32;
    int n0 = blockIdx.y * 32;
    int tx = threadIdx.x, ty = threadIdx.y;   // block (32, 8)
#pragma unroll
    for (int r = 0; r < 4; r++) {
        int kk = ty + r * 8;
        int k  = k0 + kk;
        tile[kk][tx] = (k < IN_DIM) ? W[(size_t)k * HID + n0 + tx] : 0.0f;
    }
    __syncthreads();
#pragma unroll
    for (int r = 0; r < 4; r++) {
        int nn = ty + r * 8;
        float a = tile[tx][nn];
        __nv_bfloat16 h = __float2bfloat16(a);
        float res = a - __bfloat162float(h);
        size_t o = (size_t)(n0 + nn) * K_PAD + k0 + tx;
        hi[o] = h;
        lo[o] = __float2bfloat16(res);
    }
}

// -------------------- Kernel 1: bf16x3 warp-MMA GEMM, fused A split ---------
// X[8192,512] = A[8192,3000] @ W0, via AhBh + AhBl + AlBh (fp32 accum).
// A is loaded fp32 from global, split in registers, STS'd as bf16 hi/lo.

// LDG A chunk into regs: 4 float4 per thread (128 rows x 16 segs of 4 floats)
__device__ __forceinline__ void ldgA(const float* __restrict__ Abase, int k0,
                                     int t, bool last, float4* v)
{
#pragma unroll
    for (int i = 0; i < 4; i++) {
        int lin = t + i * 512;
        int row = lin >> 4, seg = lin & 15;
        if (last && seg >= 14) {            // cols >= 3000 -> zero pad
            v[i] = make_float4(0.f, 0.f, 0.f, 0.f);
        } else {
            v[i] = *(const float4*)(Abase + (size_t)row * IN_DIM + k0 + seg * 4);
        }
    }
}

// convert + STS into stage's Ah/Al regions
__device__ __forceinline__ void stsA(uint32_t base, int t, const float4* v)
{
#pragma unroll
    for (int i = 0; i < 4; i++) {
        int lin = t + i * 512;
        int row = lin >> 4, seg = lin & 15;
        float4 a = v[i];
        __nv_bfloat16 h0 = __float2bfloat16(a.x);
        __nv_bfloat16 h1 = __float2bfloat16(a.y);
        __nv_bfloat16 h2 = __float2bfloat16(a.z);
        __nv_bfloat16 h3 = __float2bfloat16(a.w);
        __nv_bfloat162 hA = __halves2bfloat162(h0, h1);
        __nv_bfloat162 hB = __halves2bfloat162(h2, h3);
        __nv_bfloat162 lA = __halves2bfloat162(
            __float2bfloat16(a.x - __bfloat162float(h0)),
            __float2bfloat16(a.y - __bfloat162float(h1)));
        __nv_bfloat162 lB = __halves2bfloat162(
            __float2bfloat16(a.z - __bfloat162float(h2)),
            __float2bfloat16(a.w - __bfloat162float(h3)));
        uint32_t off = sw128((uint32_t)(row * 128 + seg * 8));
        uint2 hv = make_uint2(*(const uint32_t*)&hA, *(const uint32_t*)&hB);
        uint2 lv = make_uint2(*(const uint32_t*)&lA, *(const uint32_t*)&lB);
        asm volatile("st.shared.v2.u32 [%0], {%1, %2};"
                     :: "r"(base + off), "r"(hv.x), "r"(hv.y) : "memory");
        asm volatile("st.shared.v2.u32 [%0], {%1, %2};"
                     :: "r"(base + A_BYTES + off), "r"(lv.x), "r"(lv.y) : "memory");
    }
}

__device__ __forceinline__ void ldgB(uint32_t base, int k0, int t,
                                     const __nv_bfloat16* Bh,
                                     const __nv_bfloat16* Bl)
{
#pragma unroll
    for (int i = 0; i < 4; i++) {
        int lin = t + i * 512;
        int row = lin >> 3, seg = lin & 7;
        uint32_t so = sw128((uint32_t)(row * 128 + seg * 16));
        cp_async16(base + 2 * A_BYTES + so,
                   Bh + (size_t)row * K_PAD + k0 + seg * 8);
        cp_async16(base + 2 * A_BYTES + B_BYTES + so,
                   Bl + (size_t)row * K_PAD + k0 + seg * 8);
    }
}

__global__ __launch_bounds__(512, 1)
void gemm_mma_kernel(const float* __restrict__ A, float* __restrict__ Xout)
{
    extern __shared__ __align__(1024) char smem[];
    const uint32_t sb = smem_u32(smem);
    const int t    = threadIdx.x;
    const int wid  = t >> 5;
    const int lane = t & 31;
    const int wy   = wid >> 2;   // 0..3 : m group (32 rows)
    const int wx   = wid & 3;    // 0..3 : n group (64 cols)

    const float* Abase = A + (size_t)(blockIdx.y * BM) * IN_DIM;
    const __nv_bfloat16* Bh = g_Bhi + (size_t)(blockIdx.x * BN) * K_PAD;
    const __nv_bfloat16* Bl = g_Blo + (size_t)(blockIdx.x * BN) * K_PAD;

    float acc[2][8][4];
#pragma unroll
    for (int i = 0; i < 2; i++)
#pragma unroll
        for (int j = 0; j < 8; j++)
#pragma unroll
            for (int q = 0; q < 4; q++) acc[i][j][q] = 0.0f;

    const int a_row = (lane & 15);
    const int a_k8  = (lane >> 4);
    const int b_row = ((lane >> 4) << 3) + (lane & 7);
    const int b_k8  = (lane >> 3) & 1;

    // prologue: chunk 0
    {
        float4 v[4];
        ldgA(Abase, 0, t, false, v);
        stsA(sb, t, v);
        ldgB(sb, 0, t, Bh, Bl);
        cp_commit();
    }

    float4 vnext[4];
    for (int c = 0; c < NCHUNK; c++) {
        asm volatile("cp.async.wait_group 0;" ::: "memory");
        __syncthreads();

        const bool pref = (c + 1 < NCHUNK);
        if (pref) {
            ldgA(Abase, (c + 1) * BK, t, (c + 1) == NCHUNK - 1, vnext);
            ldgB(sb + ((c + 1) & 1) * STAGE, (c + 1) * BK, t, Bh, Bl);
            cp_commit();
        }

        const uint32_t base = sb + (c & 1) * STAGE;
        const uint32_t aH = base;
        const uint32_t aL = base + A_BYTES;
        const uint32_t bH = base + 2 * A_BYTES;
        const uint32_t bL = base + 2 * A_BYTES + B_BYTES;

#pragma unroll
        for (int kk = 0; kk < 4; kk++) {
            uint32_t ah[2][4], al[2][4];
#pragma unroll
            for (int mt = 0; mt < 2; mt++) {
                int row = wy * 32 + mt * 16 + a_row;
                int kcol = kk * 16 + a_k8 * 8;
                uint32_t off = sw128((uint32_t)(row * 128 + kcol * 2));
                ldmx4(ah[mt], aH + off);
                ldmx4(al[mt], aL + off);
            }
#pragma unroll
            for (int ng = 0; ng < 4; ng++) {
                int n = wx * 64 + ng * 16 + b_row;
                int kcol = kk * 16 + b_k8 * 8;
                uint32_t off = sw128((uint32_t)(n * 128 + kcol * 2));
                uint32_t bh[4], bl[4];
                ldmx4(bh, bH + off);
                ldmx4(bl, bL + off);
#pragma unroll
                for (int mt = 0; mt < 2; mt++) {
                    mma_bf16(acc[mt][2 * ng],     ah[mt], bh);
                    mma_bf16(acc[mt][2 * ng + 1], ah[mt], bh + 2);
                    mma_bf16(acc[mt][2 * ng],     al[mt], bh);
                    mma_bf16(acc[mt][2 * ng + 1], al[mt], bh + 2);
                    mma_bf16(acc[mt][2 * ng],     ah[mt], bl);
                    mma_bf16(acc[mt][2 * ng + 1], ah[mt], bl + 2);
                }
            }
        }

        if (pref) stsA(sb + ((c + 1) & 1) * STAGE, t, vnext);
        // top-of-loop __syncthreads orders these STS before next compute
    }

    // epilogue: write fp32 C
    float* dst = Xout + (size_t)(blockIdx.y * BM + wy * 32) * HID
               + blockIdx.x * BN + wx * 64;
    const int r0 = lane >> 2;
    const int c0 = (lane & 3) * 2;
#pragma unroll
    for (int mt = 0; mt < 2; mt++) {
#pragma unroll
        for (int nt = 0; nt < 8; nt++) {
            float* p0 = dst + (size_t)(mt * 16 + r0) * HID + nt * 8 + c0;
            float* p1 = dst + (size_t)(mt * 16 + r0 + 8) * HID + nt * 8 + c0;
            *(float2*)p0 = make_float2(acc[mt][nt][0], acc[mt][nt][1]);
            *(float2*)p1 = make_float2(acc[mt][nt][2], acc[mt][nt][3]);
        }
    }
}

// -------------------- Kernel 2: f0 = X@v0, f1 = X@v1 ------------------------
__global__ void fvec_kernel(const float* __restrict__ X,
                            const float* __restrict__ v0,
                            const float* __restrict__ v1,
                            float* __restrict__ f0, float* __restrict__ f1)
{
    int row  = blockIdx.x * 8 + (threadIdx.x >> 5);
    int lane = threadIdx.x & 31;
    const float4* xr = (const float4*)(X + (size_t)row * HID);
    const float4* w0 = (const float4*)v0;
    const float4* w1 = (const float4*)v1;
    float s0 = 0.f, s1 = 0.f;
#pragma unroll
    for (int i = 0; i < 4; i++) {
        int d = lane + i * 32;
        float4 x = xr[d], a = w0[d], b = w1[d];
        s0 += x.x * a.x + x.y * a.y + x.z * a.z + x.w * a.w;
        s1 += x.x * b.x + x.y * b.y + x.z * b.z + x.w * b.w;
    }
#pragma unroll
    for (int o = 16; o > 0; o >>= 1) {
        s0 += __shfl_xor_sync(0xffffffffu, s0, o);
        s1 += __shfl_xor_sync(0xffffffffu, s1, o);
    }
    if (lane == 0) { f0[row] = s0; f1[row] = s1; }
}

// -------------------- Kernel 3: sparsify graph rows -------------------------
__global__ __launch_bounds__(512)
void sparsify_kernel(const float* __restrict__ graph,
                     int* __restrict__ idx, int* __restrict__ cnt)
{
    int row = blockIdx.x;
    __shared__ int c;
    if (threadIdx.x == 0) c = 0;
    __syncthreads();
    const float4* g = (const float4*)(graph + (size_t)row * M_N);
    const int t = threadIdx.x;
    float4 v[4];
#pragma unroll
    for (int i = 0; i < 4; i++) v[i] = __ldg(&g[t + i * 512]);
#pragma unroll
    for (int i = 0; i < 4; i++) {
        int b = (t + i * 512) * 4;
        if (v[i].x != 0.0f) { int s = atomicAdd(&c, 1); if (s < MAXD) idx[row * MAXD + s] = b + 0; }
        if (v[i].y != 0.0f) { int s = atomicAdd(&c, 1); if (s < MAXD) idx[row * MAXD + s] = b + 1; }
        if (v[i].z != 0.0f) { int s = atomicAdd(&c, 1); if (s < MAXD) idx[row * MAXD + s] = b + 2; }
        if (v[i].w != 0.0f) { int s = atomicAdd(&c, 1); if (s < MAXD) idx[row * MAXD + s] = b + 3; }
    }
    __syncthreads();
    if (threadIdx.x == 0) cnt[row] = (c < MAXD) ? c : MAXD;
}

// -------------------- Kernel 4: fused attention + agg + ELU + W1 ------------
__global__ __launch_bounds__(256)
void attn_kernel(const float* __restrict__ X,
                 const float* __restrict__ f0, const float* __restrict__ f1,
                 const float* __restrict__ W1,
                 const int* __restrict__ idx, const int* __restrict__ cnt,
                 float* __restrict__ out)
{
    const int row = blockIdx.x;
    const int t   = threadIdx.x;

    __shared__ int   s_idx[MAXD];
    __shared__ float s_alpha[MAXD];
    __shared__ float red[256];
    __shared__ float s_hq[4 * HID];
    __shared__ float s_h[HID];
    __shared__ float s_part[8][32];

    const int n = cnt[row];              // >= 1 (self loop)
    for (int j = t; j < n; j += 256) s_idx[j] = idx[row * MAXD + j];
    __syncthreads();

    const float f0i = f0[row];

    float my = 0.0f, mx = -INFINITY;
    if (t < n) {
        float e   = f0i + f1[s_idx[t]];
        float sig = 1.0f / (1.0f + expf(-e));
        my = sig - 0.5f;
        mx = my;
    }
    red[t] = mx;
    __syncthreads();
#pragma unroll
    for (int o = 128; o > 0; o >>= 1) {
        if (t < o) red[t] = fmaxf(red[t], red[t + o]);
        __syncthreads();
    }
    const float m = red[0];
    __syncthreads();

    float e = 0.0f;
    if (t < n) e = expf(my - m);
    red[t] = e;
    __syncthreads();
#pragma unroll
    for (int o = 128; o > 0; o >>= 1) {
        if (t < o) red[t] += red[t + o];
        __syncthreads();
    }
    const float ssum = fmaxf(red[0], 1e-30f);
    if (t < n) s_alpha[t] = e / ssum;
    __syncthreads();

    // aggregation: quarter q handles neighbors j ≡ q (mod 4)
    const int q = t >> 6;
    const int u = t & 63;
    float4 a0 = make_float4(0.f, 0.f, 0.f, 0.f);
    float4 a1 = make_float4(0.f, 0.f, 0.f, 0.f);
    for (int j = q; j < n; j += 4) {
        const float a = s_alpha[j];
        const float4* xr = (const float4*)(X + (size_t)s_idx[j] * HID);
        float4 x0 = xr[u * 2], x1 = xr[u * 2 + 1];
        a0.x += a * x0.x; a0.y += a * x0.y; a0.z += a * x0.z; a0.w += a * x0.w;
        a1.x += a * x1.x; a1.y += a * x1.y; a1.z += a * x1.z; a1.w += a * x1.w;
    }
    ((float4*)(s_hq + q * HID))[u * 2]     = a0;
    ((float4*)(s_hq + q * HID))[u * 2 + 1] = a1;
    __syncthreads();

    if (t < 128) {
        float4 r = make_float4(0.f, 0.f, 0.f, 0.f);
#pragma unroll
        for (int qq = 0; qq < 4; qq++) {
            float4 v = ((const float4*)s_hq)[qq * 128 + t];
            r.x += v.x; r.y += v.y; r.z += v.z; r.w += v.w;
        }
        r.x = (r.x > 0.f) ? r.x : expm1f(r.x);
        r.y = (r.y > 0.f) ? r.y : expm1f(r.y);
        r.z = (r.z > 0.f) ? r.z : expm1f(r.z);
        r.w = (r.w > 0.f) ? r.w : expm1f(r.w);
        ((float4*)s_h)[t] = r;
    }
    __syncthreads();

    if (t < 240) {
        int k  = t % 30;
        int sl = t / 30;
        float p = 0.0f;
        const int d0 = sl * 64;
#pragma unroll 8
        for (int d = d0; d < d0 + 64; d++) p += s_h[d] * W1[d * LAT + k];
        s_part[sl][k] = p;
    }
    __syncthreads();
    if (t < LAT) {
        float r = 0.0f;
#pragma unroll
        for (int sl = 0; sl < 8; sl++) r += s_part[sl][t];
        out[(size_t)row * LAT + t] = r;
    }
}

// -------------------- launch -------------------------------------------------
extern "C" void kernel_launch(void* const* d_in, const int* in_sizes, int n_in,
                              void* d_out, int out_size)
{
    const float* node_features = (const float*)d_in[0]; // [8192,3000]
    const float* graph         = (const float*)d_in[1]; // [8192,8192]
    const float* W0            = (const float*)d_in[2]; // [3000,512]
    const float* v0            = (const float*)d_in[3]; // [512]
    const float* v1            = (const float*)d_in[4]; // [512]
    const float* W1            = (const float*)d_in[5]; // [512,30]
    float* out = (float*)d_out;

    float *X, *f0, *f1;
    int *idx, *cnt;
    __nv_bfloat16 *Bhi, *Blo;
    cudaGetSymbolAddress((void**)&X,   g_X);
    cudaGetSymbolAddress((void**)&f0,  g_f0);
    cudaGetSymbolAddress((void**)&f1,  g_f1);
    cudaGetSymbolAddress((void**)&idx, g_idx);
    cudaGetSymbolAddress((void**)&cnt, g_cnt);
    cudaGetSymbolAddress((void**)&Bhi, g_Bhi);
    cudaGetSymbolAddress((void**)&Blo, g_Blo);

    // one-time resources (created on the uncaptured correctness call)
    static cudaStream_t s2 = nullptr;
    static cudaEvent_t evFork = nullptr, evJoin = nullptr;
    if (s2 == nullptr) {
        cudaStreamCreateWithFlags(&s2, cudaStreamNonBlocking);
        cudaEventCreateWithFlags(&evFork, cudaEventDisableTiming);
        cudaEventCreateWithFlags(&evJoin, cudaEventDisableTiming);
        cudaFuncSetAttribute(gemm_mma_kernel,
                             cudaFuncAttributeMaxDynamicSharedMemorySize,
                             SMEM_TOTAL);
    }

    // fork: sparsify runs on s2 concurrently with the GEMM chain
    cudaEventRecord(evFork, 0);
    cudaStreamWaitEvent(s2, evFork, 0);
    sparsify_kernel<<<M_N, 512, 0, s2>>>(graph, idx, cnt);
    cudaEventRecord(evJoin, s2);

    // main chain on the default stream
    convB_kernel<<<dim3(K_PAD / 32, HID / 32), dim3(32, 8)>>>(W0, Bhi, Blo);
    gemm_mma_kernel<<<dim3(HID / BN, M_N / BM), 512, SMEM_TOTAL>>>(node_features, X);
    fvec_kernel<<<M_N / 8, 256>>>(X, v0, v1, f0, f1);

    // join: attn needs both the GEMM chain and sparsify
    cudaStreamWaitEvent(0, evJoin, 0);
    attn_kernel<<<M_N, 256>>>(X, f0, f1, W1, idx, cnt, out);
}

// round 5
// speedup vs baseline: 2.7736x; 1.2077x over previous
#include <cuda_runtime.h>
#include <cuda_fp16.h>
#include <math.h>
#include <stdint.h>

// -------------------- problem constants --------------------
#define M_N     8192
#define IN_DIM  3000
#define K_PAD   3008        // 47 * 64
#define HID     512
#define LAT     30
#define MAXD    192

#define BM      128
#define BN      256
#define BK      64
#define NCHUNK  (K_PAD / BK)   // 47

// SMEM stage layout (bytes): Ah[128x64]=16K, Al=16K, Bh[256x64]=32K
#define A_BYTES   16384
#define B_BYTES   32768
#define STAGE     (2 * A_BYTES + B_BYTES)        // 65536
#define SMEM_TOTAL (2 * STAGE)                   // 131072

// -------------------- static device scratch --------------------
__device__ __align__(16) float g_X[(size_t)M_N * HID];        // 16 MB
__device__ float g_f0[M_N];
__device__ float g_f1[M_N];
__device__ int   g_idx[M_N * MAXD];
__device__ int   g_cnt[M_N];
__device__ __align__(16) __half g_Bhi[(size_t)HID * K_PAD];   // [n][k] fp16

// -------------------- PTX helpers --------------------
__device__ __forceinline__ uint32_t smem_u32(const void* p) {
    uint32_t a;
    asm("{ .reg .u64 t; cvta.to.shared.u64 t, %1; cvt.u32.u64 %0, t; }"
        : "=r"(a) : "l"(p));
    return a;
}

__device__ __forceinline__ uint32_t sw128(uint32_t off) {
    return off ^ ((off >> 3) & 0x70);
}

__device__ __forceinline__ void cp_async16(uint32_t dst, const void* src) {
    asm volatile("cp.async.cg.shared.global [%0], [%1], 16;"
                 :: "r"(dst), "l"(src));
}
__device__ __forceinline__ void cp_commit() {
    asm volatile("cp.async.commit_group;" ::: "memory");
}

__device__ __forceinline__ void ldmx4(uint32_t* r, uint32_t addr) {
    asm volatile("ldmatrix.sync.aligned.m8n8.x4.shared.b16 {%0,%1,%2,%3}, [%4];"
                 : "=r"(r[0]), "=r"(r[1]), "=r"(r[2]), "=r"(r[3]) : "r"(addr));
}

__device__ __forceinline__ void mma_fp16(float* d, const uint32_t* a,
                                         const uint32_t* b) {
    asm volatile(
        "mma.sync.aligned.m16n8k16.row.col.f32.f16.f16.f32 "
        "{%0,%1,%2,%3}, {%4,%5,%6,%7}, {%8,%9}, {%0,%1,%2,%3};"
        : "+f"(d[0]), "+f"(d[1]), "+f"(d[2]), "+f"(d[3])
        : "r"(a[0]), "r"(a[1]), "r"(a[2]), "r"(a[3]), "r"(b[0]), "r"(b[1]));
}

// -------------------- Kernel 0: transpose W0 -> [n][k] fp16 -----------------
__global__ void convB_kernel(const float* __restrict__ W,
                             __half* __restrict__ hi)
{
    __shared__ float tile[32][33];
    int k0 = blockIdx.x * 32;
    int n0 = blockIdx.y * 32;
    int tx = threadIdx.x, ty = threadIdx.y;   // block (32, 8)
#pragma unroll
    for (int r = 0; r < 4; r++) {
        int kk = ty + r * 8;
        int k  = k0 + kk;
        tile[kk][tx] = (k < IN_DIM) ? W[(size_t)k * HID + n0 + tx] : 0.0f;
    }
    __syncthreads();
#pragma unroll
    for (int r = 0; r < 4; r++) {
        int nn = ty + r * 8;
        hi[(size_t)(n0 + nn) * K_PAD + k0 + tx] = __float2half(tile[tx][nn]);
    }
}

// -------------------- Kernel 1: fp16x2 warp-MMA GEMM, fused A split ---------
// X[8192,512] = A[8192,3000] @ W0 via (Ah + Al) @ Bh, fp32 accum.

__device__ __forceinline__ void ldgA(const float* __restrict__ Abase, int k0,
                                     int t, bool last, float4* v)
{
#pragma unroll
    for (int i = 0; i < 4; i++) {
        int lin = t + i * 512;
        int row = lin >> 4, seg = lin & 15;
        if (last && seg >= 14) {            // cols >= 3000 -> zero pad
            v[i] = make_float4(0.f, 0.f, 0.f, 0.f);
        } else {
            v[i] = *(const float4*)(Abase + (size_t)row * IN_DIM + k0 + seg * 4);
        }
    }
}

__device__ __forceinline__ void stsA(uint32_t base, int t, const float4* v)
{
#pragma unroll
    for (int i = 0; i < 4; i++) {
        int lin = t + i * 512;
        int row = lin >> 4, seg = lin & 15;
        float4 a = v[i];
        __half h0 = __float2half(a.x);
        __half h1 = __float2half(a.y);
        __half h2 = __float2half(a.z);
        __half h3 = __float2half(a.w);
        __half2 hA = __halves2half2(h0, h1);
        __half2 hB = __halves2half2(h2, h3);
        __half2 lA = __halves2half2(__float2half(a.x - __half2float(h0)),
                                    __float2half(a.y - __half2float(h1)));
        __half2 lB = __halves2half2(__float2half(a.z - __half2float(h2)),
                                    __float2half(a.w - __half2float(h3)));
        uint32_t off = sw128((uint32_t)(row * 128 + seg * 8));
        asm volatile("st.shared.v2.u32 [%0], {%1, %2};"
                     :: "r"(base + off),
                        "r"(*(const uint32_t*)&hA), "r"(*(const uint32_t*)&hB)
                     : "memory");
        asm volatile("st.shared.v2.u32 [%0], {%1, %2};"
                     :: "r"(base + A_BYTES + off),
                        "r"(*(const uint32_t*)&lA), "r"(*(const uint32_t*)&lB)
                     : "memory");
    }
}

__device__ __forceinline__ void ldgB(uint32_t base, int k0, int t,
                                     const __half* Bh)
{
#pragma unroll
    for (int i = 0; i < 4; i++) {
        int lin = t + i * 512;
        int row = lin >> 3, seg = lin & 7;
        uint32_t so = sw128((uint32_t)(row * 128 + seg * 16));
        cp_async16(base + 2 * A_BYTES + so,
                   Bh + (size_t)row * K_PAD + k0 + seg * 8);
    }
}

__global__ __launch_bounds__(512, 1)
void gemm_mma_kernel(const float* __restrict__ A, float* __restrict__ Xout)
{
    extern __shared__ __align__(1024) char smem[];
    const uint32_t sb = smem_u32(smem);
    const int t    = threadIdx.x;
    const int wid  = t >> 5;
    const int lane = t & 31;
    const int wy   = wid >> 2;   // 0..3 : m group (32 rows)
    const int wx   = wid & 3;    // 0..3 : n group (64 cols)

    const float* Abase = A + (size_t)(blockIdx.y * BM) * IN_DIM;
    const __half* Bh = g_Bhi + (size_t)(blockIdx.x * BN) * K_PAD;

    float acc[2][8][4];
#pragma unroll
    for (int i = 0; i < 2; i++)
#pragma unroll
        for (int j = 0; j < 8; j++)
#pragma unroll
            for (int q = 0; q < 4; q++) acc[i][j][q] = 0.0f;

    const int a_row = (lane & 15);
    const int a_k8  = (lane >> 4);
    const int b_row = ((lane >> 4) << 3) + (lane & 7);
    const int b_k8  = (lane >> 3) & 1;

    // prologue: chunk 0
    {
        float4 v[4];
        ldgA(Abase, 0, t, false, v);
        stsA(sb, t, v);
        ldgB(sb, 0, t, Bh);
        cp_commit();
    }

    float4 vnext[4];
    for (int c = 0; c < NCHUNK; c++) {
        asm volatile("cp.async.wait_group 0;" ::: "memory");
        __syncthreads();

        const bool pref = (c + 1 < NCHUNK);
        if (pref) {
            ldgA(Abase, (c + 1) * BK, t, (c + 1) == NCHUNK - 1, vnext);
            ldgB(sb + ((c + 1) & 1) * STAGE, (c + 1) * BK, t, Bh);
            cp_commit();
        }

        const uint32_t base = sb + (c & 1) * STAGE;
        const uint32_t aH = base;
        const uint32_t aL = base + A_BYTES;
        const uint32_t bH = base + 2 * A_BYTES;

#pragma unroll
        for (int kk = 0; kk < 4; kk++) {
            uint32_t ah[2][4], al[2][4];
#pragma unroll
            for (int mt = 0; mt < 2; mt++) {
                int row = wy * 32 + mt * 16 + a_row;
                int kcol = kk * 16 + a_k8 * 8;
                uint32_t off = sw128((uint32_t)(row * 128 + kcol * 2));
                ldmx4(ah[mt], aH + off);
                ldmx4(al[mt], aL + off);
            }
#pragma unroll
            for (int ng = 0; ng < 4; ng++) {
                int n = wx * 64 + ng * 16 + b_row;
                int kcol = kk * 16 + b_k8 * 8;
                uint32_t off = sw128((uint32_t)(n * 128 + kcol * 2));
                uint32_t bh[4];
                ldmx4(bh, bH + off);
#pragma unroll
                for (int mt = 0; mt < 2; mt++) {
                    mma_fp16(acc[mt][2 * ng],     ah[mt], bh);
                    mma_fp16(acc[mt][2 * ng + 1], ah[mt], bh + 2);
                    mma_fp16(acc[mt][2 * ng],     al[mt], bh);
                    mma_fp16(acc[mt][2 * ng + 1], al[mt], bh + 2);
                }
            }
        }

        if (pref) stsA(sb + ((c + 1) & 1) * STAGE, t, vnext);
        // top-of-loop __syncthreads orders these STS before next compute
    }

    // epilogue: write fp32 C
    float* dst = Xout + (size_t)(blockIdx.y * BM + wy * 32) * HID
               + blockIdx.x * BN + wx * 64;
    const int r0 = lane >> 2;
    const int c0 = (lane & 3) * 2;
#pragma unroll
    for (int mt = 0; mt < 2; mt++) {
#pragma unroll
        for (int nt = 0; nt < 8; nt++) {
            float* p0 = dst + (size_t)(mt * 16 + r0) * HID + nt * 8 + c0;
            float* p1 = dst + (size_t)(mt * 16 + r0 + 8) * HID + nt * 8 + c0;
            *(float2*)p0 = make_float2(acc[mt][nt][0], acc[mt][nt][1]);
            *(float2*)p1 = make_float2(acc[mt][nt][2], acc[mt][nt][3]);
        }
    }
}

// -------------------- Kernel 2: f0 = X@v0, f1 = X@v1 ------------------------
__global__ void fvec_kernel(const float* __restrict__ X,
                            const float* __restrict__ v0,
                            const float* __restrict__ v1,
                            float* __restrict__ f0, float* __restrict__ f1)
{
    int row  = blockIdx.x * 8 + (threadIdx.x >> 5);
    int lane = threadIdx.x & 31;
    const float4* xr = (const float4*)(X + (size_t)row * HID);
    const float4* w0 = (const float4*)v0;
    const float4* w1 = (const float4*)v1;
    float s0 = 0.f, s1 = 0.f;
#pragma unroll
    for (int i = 0; i < 4; i++) {
        int d = lane + i * 32;
        float4 x = xr[d], a = w0[d], b = w1[d];
        s0 += x.x * a.x + x.y * a.y + x.z * a.z + x.w * a.w;
        s1 += x.x * b.x + x.y * b.y + x.z * b.z + x.w * b.w;
    }
#pragma unroll
    for (int o = 16; o > 0; o >>= 1) {
        s0 += __shfl_xor_sync(0xffffffffu, s0, o);
        s1 += __shfl_xor_sync(0xffffffffu, s1, o);
    }
    if (lane == 0) { f0[row] = s0; f1[row] = s1; }
}

// -------------------- Kernel 3: sparsify graph rows -------------------------
__global__ __launch_bounds__(512)
void sparsify_kernel(const float* __restrict__ graph,
                     int* __restrict__ idx, int* __restrict__ cnt)
{
    int row = blockIdx.x;
    __shared__ int c;
    if (threadIdx.x == 0) c = 0;
    __syncthreads();
    const float4* g = (const float4*)(graph + (size_t)row * M_N);
    const int t = threadIdx.x;
    float4 v[4];
#pragma unroll
    for (int i = 0; i < 4; i++) v[i] = __ldg(&g[t + i * 512]);
#pragma unroll
    for (int i = 0; i < 4; i++) {
        int b = (t + i * 512) * 4;
        if (v[i].x != 0.0f) { int s = atomicAdd(&c, 1); if (s < MAXD) idx[row * MAXD + s] = b + 0; }
        if (v[i].y != 0.0f) { int s = atomicAdd(&c, 1); if (s < MAXD) idx[row * MAXD + s] = b + 1; }
        if (v[i].z != 0.0f) { int s = atomicAdd(&c, 1); if (s < MAXD) idx[row * MAXD + s] = b + 2; }
        if (v[i].w != 0.0f) { int s = atomicAdd(&c, 1); if (s < MAXD) idx[row * MAXD + s] = b + 3; }
    }
    __syncthreads();
    if (threadIdx.x == 0) cnt[row] = (c < MAXD) ? c : MAXD;
}

// -------------------- Kernel 4: fused attention + agg + ELU + W1 ------------
__global__ __launch_bounds__(256)
void attn_kernel(const float* __restrict__ X,
                 const float* __restrict__ f0, const float* __restrict__ f1,
                 const float* __restrict__ W1,
                 const int* __restrict__ idx, const int* __restrict__ cnt,
                 float* __restrict__ out)
{
    const int row = blockIdx.x;
    const int t   = threadIdx.x;

    __shared__ int   s_idx[MAXD];
    __shared__ float s_alpha[MAXD];
    __shared__ float red[256];
    __shared__ float s_hq[4 * HID];
    __shared__ float s_h[HID];
    __shared__ float s_part[8][32];

    const int n = cnt[row];              // >= 1 (self loop)
    for (int j = t; j < n; j += 256) s_idx[j] = idx[row * MAXD + j];
    __syncthreads();

    const float f0i = f0[row];

    float my = 0.0f, mx = -INFINITY;
    if (t < n) {
        float e   = f0i + f1[s_idx[t]];
        float sig = 1.0f / (1.0f + expf(-e));
        my = sig - 0.5f;
        mx = my;
    }
    red[t] = mx;
    __syncthreads();
#pragma unroll
    for (int o = 128; o > 0; o >>= 1) {
        if (t < o) red[t] = fmaxf(red[t], red[t + o]);
        __syncthreads();
    }
    const float m = red[0];
    __syncthreads();

    float e = 0.0f;
    if (t < n) e = expf(my - m);
    red[t] = e;
    __syncthreads();
#pragma unroll
    for (int o = 128; o > 0; o >>= 1) {
        if (t < o) red[t] += red[t + o];
        __syncthreads();
    }
    const float ssum = fmaxf(red[0], 1e-30f);
    if (t < n) s_alpha[t] = e / ssum;
    __syncthreads();

    // aggregation: quarter q handles neighbors j ≡ q (mod 4)
    const int q = t >> 6;
    const int u = t & 63;
    float4 a0 = make_float4(0.f, 0.f, 0.f, 0.f);
    float4 a1 = make_float4(0.f, 0.f, 0.f, 0.f);
    for (int j = q; j < n; j += 4) {
        const float a = s_alpha[j];
        const float4* xr = (const float4*)(X + (size_t)s_idx[j] * HID);
        float4 x0 = xr[u * 2], x1 = xr[u * 2 + 1];
        a0.x += a * x0.x; a0.y += a * x0.y; a0.z += a * x0.z; a0.w += a * x0.w;
        a1.x += a * x1.x; a1.y += a * x1.y; a1.z += a * x1.z; a1.w += a * x1.w;
    }
    ((float4*)(s_hq + q * HID))[u * 2]     = a0;
    ((float4*)(s_hq + q * HID))[u * 2 + 1] = a1;
    __syncthreads();

    if (t < 128) {
        float4 r = make_float4(0.f, 0.f, 0.f, 0.f);
#pragma unroll
        for (int qq = 0; qq < 4; qq++) {
            float4 v = ((const float4*)s_hq)[qq * 128 + t];
            r.x += v.x; r.y += v.y; r.z += v.z; r.w += v.w;
        }
        r.x = (r.x > 0.f) ? r.x : expm1f(r.x);
        r.y = (r.y > 0.f) ? r.y : expm1f(r.y);
        r.z = (r.z > 0.f) ? r.z : expm1f(r.z);
        r.w = (r.w > 0.f) ? r.w : expm1f(r.w);
        ((float4*)s_h)[t] = r;
    }
    __syncthreads();

    if (t < 240) {
        int k  = t % 30;
        int sl = t / 30;
        float p = 0.0f;
        const int d0 = sl * 64;
#pragma unroll 8
        for (int d = d0; d < d0 + 64; d++) p += s_h[d] * W1[d * LAT + k];
        s_part[sl][k] = p;
    }
    __syncthreads();
    if (t < LAT) {
        float r = 0.0f;
#pragma unroll
        for (int sl = 0; sl < 8; sl++) r += s_part[sl][t];
        out[(size_t)row * LAT + t] = r;
    }
}

// -------------------- launch -------------------------------------------------
extern "C" void kernel_launch(void* const* d_in, const int* in_sizes, int n_in,
                              void* d_out, int out_size)
{
    const float* node_features = (const float*)d_in[0]; // [8192,3000]
    const float* graph         = (const float*)d_in[1]; // [8192,8192]
    const float* W0            = (const float*)d_in[2]; // [3000,512]
    const float* v0            = (const float*)d_in[3]; // [512]
    const float* v1            = (const float*)d_in[4]; // [512]
    const float* W1            = (const float*)d_in[5]; // [512,30]
    float* out = (float*)d_out;

    float *X, *f0, *f1;
    int *idx, *cnt;
    __half *Bhi;
    cudaGetSymbolAddress((void**)&X,   g_X);
    cudaGetSymbolAddress((void**)&f0,  g_f0);
    cudaGetSymbolAddress((void**)&f1,  g_f1);
    cudaGetSymbolAddress((void**)&idx, g_idx);
    cudaGetSymbolAddress((void**)&cnt, g_cnt);
    cudaGetSymbolAddress((void**)&Bhi, g_Bhi);

    // one-time resources (created on the uncaptured correctness call)
    static cudaStream_t s2 = nullptr;
    static cudaEvent_t evFork = nullptr, evJoin = nullptr;
    if (s2 == nullptr) {
        cudaStreamCreateWithFlags(&s2, cudaStreamNonBlocking);
        cudaEventCreateWithFlags(&evFork, cudaEventDisableTiming);
        cudaEventCreateWithFlags(&evJoin, cudaEventDisableTiming);
        cudaFuncSetAttribute(gemm_mma_kernel,
                             cudaFuncAttributeMaxDynamicSharedMemorySize,
                             SMEM_TOTAL);
    }

    // fork: sparsify runs on s2 concurrently with the GEMM chain
    cudaEventRecord(evFork, 0);
    cudaStreamWaitEvent(s2, evFork, 0);
    sparsify_kernel<<<M_N, 512, 0, s2>>>(graph, idx, cnt);
    cudaEventRecord(evJoin, s2);

    // main chain on the default stream
    convB_kernel<<<dim3(K_PAD / 32, HID / 32), dim3(32, 8)>>>(W0, Bhi);
    gemm_mma_kernel<<<dim3(HID / BN, M_N / BM), 512, SMEM_TOTAL>>>(node_features, X);
    fvec_kernel<<<M_N / 8, 256>>>(X, v0, v1, f0, f1);

    // join: attn needs both the GEMM chain and sparsify
    cudaStreamWaitEvent(0, evJoin, 0);
    attn_kernel<<<M_N, 256>>>(X, f0, f1, W1, idx, cnt, out);
}

// round 6
// speedup vs baseline: 3.7901x; 1.3665x over previous
#include <cuda_runtime.h>
#include <cuda_fp16.h>
#include <math.h>
#include <stdint.h>

// -------------------- problem constants --------------------
#define M_N     8192
#define IN_DIM  3000
#define K_PAD   3008        // 47 * 64
#define HID     512
#define LAT     30
#define MAXD    192

#define BM      128
#define BN      256
#define BK      64
#define NCHUNK  (K_PAD / BK)   // 47

// SMEM stage layout (bytes): Ah[128x64]=16K, Bh[256x64]=32K
#define A_BYTES   16384
#define B_BYTES   32768
#define STAGE     (A_BYTES + B_BYTES)            // 49152
#define SMEM_TOTAL (2 * STAGE)                   // 98304

// -------------------- static device scratch --------------------
__device__ __align__(16) __half g_Xh[(size_t)M_N * HID];      // 8 MB fp16 X
__device__ float g_f0[M_N];
__device__ float g_f1[M_N];
__device__ int   g_idx[M_N * MAXD];
__device__ int   g_cnt[M_N];
__device__ __align__(16) __half g_Bhi[(size_t)HID * K_PAD];   // [n][k] fp16

// -------------------- PTX helpers --------------------
__device__ __forceinline__ uint32_t smem_u32(const void* p) {
    uint32_t a;
    asm("{ .reg .u64 t; cvta.to.shared.u64 t, %1; cvt.u32.u64 %0, t; }"
        : "=r"(a) : "l"(p));
    return a;
}

__device__ __forceinline__ uint32_t sw128(uint32_t off) {
    return off ^ ((off >> 3) & 0x70);
}

__device__ __forceinline__ void cp_async16(uint32_t dst, const void* src) {
    asm volatile("cp.async.cg.shared.global [%0], [%1], 16;"
                 :: "r"(dst), "l"(src));
}
__device__ __forceinline__ void cp_commit() {
    asm volatile("cp.async.commit_group;" ::: "memory");
}

__device__ __forceinline__ void ldmx4(uint32_t* r, uint32_t addr) {
    asm volatile("ldmatrix.sync.aligned.m8n8.x4.shared.b16 {%0,%1,%2,%3}, [%4];"
                 : "=r"(r[0]), "=r"(r[1]), "=r"(r[2]), "=r"(r[3]) : "r"(addr));
}

__device__ __forceinline__ void mma_fp16(float* d, const uint32_t* a,
                                         const uint32_t* b) {
    asm volatile(
        "mma.sync.aligned.m16n8k16.row.col.f32.f16.f16.f32 "
        "{%0,%1,%2,%3}, {%4,%5,%6,%7}, {%8,%9}, {%0,%1,%2,%3};"
        : "+f"(d[0]), "+f"(d[1]), "+f"(d[2]), "+f"(d[3])
        : "r"(a[0]), "r"(a[1]), "r"(a[2]), "r"(a[3]), "r"(b[0]), "r"(b[1]));
}

// -------------------- Kernel 0: transpose W0 -> [n][k] fp16 -----------------
__global__ void convB_kernel(const float* __restrict__ W,
                             __half* __restrict__ hi)
{
    __shared__ float tile[32][33];
    int k0 = blockIdx.x * 32;
    int n0 = blockIdx.y * 32;
    int tx = threadIdx.x, ty = threadIdx.y;   // block (32, 8)
#pragma unroll
    for (int r = 0; r < 4; r++) {
        int kk = ty + r * 8;
        int k  = k0 + kk;
        tile[kk][tx] = (k < IN_DIM) ? W[(size_t)k * HID + n0 + tx] : 0.0f;
    }
    __syncthreads();
#pragma unroll
    for (int r = 0; r < 4; r++) {
        int nn = ty + r * 8;
        hi[(size_t)(n0 + nn) * K_PAD + k0 + tx] = __float2half(tile[tx][nn]);
    }
}

// -------------------- Kernel 1: fp16 warp-MMA GEMM, fused A convert ---------
// Xh[8192,512] = fp16( A[8192,3000] @ W0 ), fp32 accum inside.

__device__ __forceinline__ void ldgA(const float* __restrict__ Abase, int k0,
                                     int t, bool last, float4* v)
{
#pragma unroll
    for (int i = 0; i < 4; i++) {
        int lin = t + i * 512;
        int row = lin >> 4, seg = lin & 15;
        if (last && seg >= 14) {            // cols >= 3000 -> zero pad
            v[i] = make_float4(0.f, 0.f, 0.f, 0.f);
        } else {
            v[i] = *(const float4*)(Abase + (size_t)row * IN_DIM + k0 + seg * 4);
        }
    }
}

__device__ __forceinline__ void stsA(uint32_t base, int t, const float4* v)
{
#pragma unroll
    for (int i = 0; i < 4; i++) {
        int lin = t + i * 512;
        int row = lin >> 4, seg = lin & 15;
        float4 a = v[i];
        __half2 hA = __floats2half2_rn(a.x, a.y);
        __half2 hB = __floats2half2_rn(a.z, a.w);
        uint32_t off = sw128((uint32_t)(row * 128 + seg * 8));
        asm volatile("st.shared.v2.u32 [%0], {%1, %2};"
                     :: "r"(base + off),
                        "r"(*(const uint32_t*)&hA), "r"(*(const uint32_t*)&hB)
                     : "memory");
    }
}

__device__ __forceinline__ void ldgB(uint32_t base, int k0, int t,
                                     const __half* Bh)
{
#pragma unroll
    for (int i = 0; i < 4; i++) {
        int lin = t + i * 512;
        int row = lin >> 3, seg = lin & 7;
        uint32_t so = sw128((uint32_t)(row * 128 + seg * 16));
        cp_async16(base + A_BYTES + so,
                   Bh + (size_t)row * K_PAD + k0 + seg * 8);
    }
}

__global__ __launch_bounds__(512, 1)
void gemm_mma_kernel(const float* __restrict__ A, __half* __restrict__ Xout)
{
    extern __shared__ __align__(1024) char smem[];
    const uint32_t sb = smem_u32(smem);
    const int t    = threadIdx.x;
    const int wid  = t >> 5;
    const int lane = t & 31;
    const int wy   = wid >> 2;   // 0..3 : m group (32 rows)
    const int wx   = wid & 3;    // 0..3 : n group (64 cols)

    const float* Abase = A + (size_t)(blockIdx.y * BM) * IN_DIM;
    const __half* Bh = g_Bhi + (size_t)(blockIdx.x * BN) * K_PAD;

    float acc[2][8][4];
#pragma unroll
    for (int i = 0; i < 2; i++)
#pragma unroll
        for (int j = 0; j < 8; j++)
#pragma unroll
            for (int q = 0; q < 4; q++) acc[i][j][q] = 0.0f;

    const int a_row = (lane & 15);
    const int a_k8  = (lane >> 4);
    const int b_row = ((lane >> 4) << 3) + (lane & 7);
    const int b_k8  = (lane >> 3) & 1;

    // prologue: chunk 0
    {
        float4 v[4];
        ldgA(Abase, 0, t, false, v);
        stsA(sb, t, v);
        ldgB(sb, 0, t, Bh);
        cp_commit();
    }

    float4 vnext[4];
    for (int c = 0; c < NCHUNK; c++) {
        asm volatile("cp.async.wait_group 0;" ::: "memory");
        __syncthreads();

        const bool pref = (c + 1 < NCHUNK);
        if (pref) {
            ldgA(Abase, (c + 1) * BK, t, (c + 1) == NCHUNK - 1, vnext);
            ldgB(sb + ((c + 1) & 1) * STAGE, (c + 1) * BK, t, Bh);
            cp_commit();
        }

        const uint32_t base = sb + (c & 1) * STAGE;
        const uint32_t aH = base;
        const uint32_t bH = base + A_BYTES;

#pragma unroll
        for (int kk = 0; kk < 4; kk++) {
            uint32_t ah[2][4];
#pragma unroll
            for (int mt = 0; mt < 2; mt++) {
                int row = wy * 32 + mt * 16 + a_row;
                int kcol = kk * 16 + a_k8 * 8;
                uint32_t off = sw128((uint32_t)(row * 128 + kcol * 2));
                ldmx4(ah[mt], aH + off);
            }
#pragma unroll
            for (int ng = 0; ng < 4; ng++) {
                int n = wx * 64 + ng * 16 + b_row;
                int kcol = kk * 16 + b_k8 * 8;
                uint32_t off = sw128((uint32_t)(n * 128 + kcol * 2));
                uint32_t bh[4];
                ldmx4(bh, bH + off);
#pragma unroll
                for (int mt = 0; mt < 2; mt++) {
                    mma_fp16(acc[mt][2 * ng],     ah[mt], bh);
                    mma_fp16(acc[mt][2 * ng + 1], ah[mt], bh + 2);
                }
            }
        }

        if (pref) stsA(sb + ((c + 1) & 1) * STAGE, t, vnext);
        // top-of-loop __syncthreads orders these STS before next compute
    }

    // epilogue: write fp16 X
    __half* dst = Xout + (size_t)(blockIdx.y * BM + wy * 32) * HID
                + blockIdx.x * BN + wx * 64;
    const int r0 = lane >> 2;
    const int c0 = (lane & 3) * 2;
#pragma unroll
    for (int mt = 0; mt < 2; mt++) {
#pragma unroll
        for (int nt = 0; nt < 8; nt++) {
            __half2 h01 = __floats2half2_rn(acc[mt][nt][0], acc[mt][nt][1]);
            __half2 h23 = __floats2half2_rn(acc[mt][nt][2], acc[mt][nt][3]);
            *(__half2*)(dst + (size_t)(mt * 16 + r0) * HID + nt * 8 + c0) = h01;
            *(__half2*)(dst + (size_t)(mt * 16 + r0 + 8) * HID + nt * 8 + c0) = h23;
        }
    }
}

// -------------------- Kernel 2: f0 = X@v0, f1 = X@v1 (fp16 X) ---------------
__global__ void fvec_kernel(const __half* __restrict__ Xh,
                            const float* __restrict__ v0,
                            const float* __restrict__ v1,
                            float* __restrict__ f0, float* __restrict__ f1)
{
    int row  = blockIdx.x * 8 + (threadIdx.x >> 5);
    int lane = threadIdx.x & 31;
    const uint4* xr = (const uint4*)(Xh + (size_t)row * HID);  // 64 uint4/row
    const float4* w0 = (const float4*)v0;
    const float4* w1 = (const float4*)v1;
    float s0 = 0.f, s1 = 0.f;
#pragma unroll
    for (int i = 0; i < 2; i++) {
        int u = lane + i * 32;            // uint4 index: 8 halves
        uint4 xv = xr[u];
        const __half2* xp = (const __half2*)&xv;
#pragma unroll
        for (int p = 0; p < 2; p++) {     // two float4 groups of 4
            float2 e0 = __half22float2(xp[p * 2 + 0]);
            float2 e1 = __half22float2(xp[p * 2 + 1]);
            float4 a = w0[u * 2 + p];
            float4 b = w1[u * 2 + p];
            s0 += e0.x * a.x + e0.y * a.y + e1.x * a.z + e1.y * a.w;
            s1 += e0.x * b.x + e0.y * b.y + e1.x * b.z + e1.y * b.w;
        }
    }
#pragma unroll
    for (int o = 16; o > 0; o >>= 1) {
        s0 += __shfl_xor_sync(0xffffffffu, s0, o);
        s1 += __shfl_xor_sync(0xffffffffu, s1, o);
    }
    if (lane == 0) { f0[row] = s0; f1[row] = s1; }
}

// -------------------- Kernel 3: sparsify graph rows -------------------------
__global__ __launch_bounds__(512)
void sparsify_kernel(const float* __restrict__ graph,
                     int* __restrict__ idx, int* __restrict__ cnt)
{
    int row = blockIdx.x;
    __shared__ int c;
    if (threadIdx.x == 0) c = 0;
    __syncthreads();
    const float4* g = (const float4*)(graph + (size_t)row * M_N);
    const int t = threadIdx.x;
    float4 v[4];
#pragma unroll
    for (int i = 0; i < 4; i++) v[i] = __ldg(&g[t + i * 512]);
#pragma unroll
    for (int i = 0; i < 4; i++) {
        int b = (t + i * 512) * 4;
        if (v[i].x != 0.0f) { int s = atomicAdd(&c, 1); if (s < MAXD) idx[row * MAXD + s] = b + 0; }
        if (v[i].y != 0.0f) { int s = atomicAdd(&c, 1); if (s < MAXD) idx[row * MAXD + s] = b + 1; }
        if (v[i].z != 0.0f) { int s = atomicAdd(&c, 1); if (s < MAXD) idx[row * MAXD + s] = b + 2; }
        if (v[i].w != 0.0f) { int s = atomicAdd(&c, 1); if (s < MAXD) idx[row * MAXD + s] = b + 3; }
    }
    __syncthreads();
    if (threadIdx.x == 0) cnt[row] = (c < MAXD) ? c : MAXD;
}

// -------------------- Kernel 4: fused attention + agg + ELU + W1 ------------
__global__ __launch_bounds__(256)
void attn_kernel(const __half* __restrict__ Xh,
                 const float* __restrict__ f0, const float* __restrict__ f1,
                 const float* __restrict__ W1,
                 const int* __restrict__ idx, const int* __restrict__ cnt,
                 float* __restrict__ out)
{
    const int row = blockIdx.x;
    const int t   = threadIdx.x;

    __shared__ int   s_idx[MAXD];
    __shared__ float s_alpha[MAXD];
    __shared__ float red[256];
    __shared__ float s_hq[4 * HID];
    __shared__ float s_h[HID];
    __shared__ float s_part[8][32];

    const int n = cnt[row];              // >= 1 (self loop)
    for (int j = t; j < n; j += 256) s_idx[j] = idx[row * MAXD + j];
    __syncthreads();

    const float f0i = f0[row];

    float my = 0.0f, mx = -INFINITY;
    if (t < n) {
        float e   = f0i + f1[s_idx[t]];
        float sig = 1.0f / (1.0f + expf(-e));
        my = sig - 0.5f;
        mx = my;
    }
    red[t] = mx;
    __syncthreads();
#pragma unroll
    for (int o = 128; o > 0; o >>= 1) {
        if (t < o) red[t] = fmaxf(red[t], red[t + o]);
        __syncthreads();
    }
    const float m = red[0];
    __syncthreads();

    float e = 0.0f;
    if (t < n) e = expf(my - m);
    red[t] = e;
    __syncthreads();
#pragma unroll
    for (int o = 128; o > 0; o >>= 1) {
        if (t < o) red[t] += red[t + o];
        __syncthreads();
    }
    const float ssum = fmaxf(red[0], 1e-30f);
    if (t < n) s_alpha[t] = e / ssum;
    __syncthreads();

    // aggregation: quarter q handles neighbors j ≡ q (mod 4);
    // each thread owns 8 output cols = one uint4 (8 halves) per neighbor
    const int q = t >> 6;
    const int u = t & 63;
    float acc[8];
#pragma unroll
    for (int i = 0; i < 8; i++) acc[i] = 0.0f;
    for (int j = q; j < n; j += 4) {
        const float a = s_alpha[j];
        const uint4 xv = *((const uint4*)(Xh + (size_t)s_idx[j] * HID) + u);
        const __half2* xp = (const __half2*)&xv;
#pragma unroll
        for (int p = 0; p < 4; p++) {
            float2 f = __half22float2(xp[p]);
            acc[2 * p]     += a * f.x;
            acc[2 * p + 1] += a * f.y;
        }
    }
    ((float4*)(s_hq + q * HID))[u * 2]     =
        make_float4(acc[0], acc[1], acc[2], acc[3]);
    ((float4*)(s_hq + q * HID))[u * 2 + 1] =
        make_float4(acc[4], acc[5], acc[6], acc[7]);
    __syncthreads();

    if (t < 128) {
        float4 r = make_float4(0.f, 0.f, 0.f, 0.f);
#pragma unroll
        for (int qq = 0; qq < 4; qq++) {
            float4 v = ((const float4*)s_hq)[qq * 128 + t];
            r.x += v.x; r.y += v.y; r.z += v.z; r.w += v.w;
        }
        r.x = (r.x > 0.f) ? r.x : expm1f(r.x);
        r.y = (r.y > 0.f) ? r.y : expm1f(r.y);
        r.z = (r.z > 0.f) ? r.z : expm1f(r.z);
        r.w = (r.w > 0.f) ? r.w : expm1f(r.w);
        ((float4*)s_h)[t] = r;
    }
    __syncthreads();

    if (t < 240) {
        int k  = t % 30;
        int sl = t / 30;
        float p = 0.0f;
        const int d0 = sl * 64;
#pragma unroll 8
        for (int d = d0; d < d0 + 64; d++) p += s_h[d] * W1[d * LAT + k];
        s_part[sl][k] = p;
    }
    __syncthreads();
    if (t < LAT) {
        float r = 0.0f;
#pragma unroll
        for (int sl = 0; sl < 8; sl++) r += s_part[sl][t];
        out[(size_t)row * LAT + t] = r;
    }
}

// -------------------- launch -------------------------------------------------
extern "C" void kernel_launch(void* const* d_in, const int* in_sizes, int n_in,
                              void* d_out, int out_size)
{
    const float* node_features = (const float*)d_in[0]; // [8192,3000]
    const float* graph         = (const float*)d_in[1]; // [8192,8192]
    const float* W0            = (const float*)d_in[2]; // [3000,512]
    const float* v0            = (const float*)d_in[3]; // [512]
    const float* v1            = (const float*)d_in[4]; // [512]
    const float* W1            = (const float*)d_in[5]; // [512,30]
    float* out = (float*)d_out;

    __half *Xh, *Bhi;
    float *f0, *f1;
    int *idx, *cnt;
    cudaGetSymbolAddress((void**)&Xh,  g_Xh);
    cudaGetSymbolAddress((void**)&f0,  g_f0);
    cudaGetSymbolAddress((void**)&f1,  g_f1);
    cudaGetSymbolAddress((void**)&idx, g_idx);
    cudaGetSymbolAddress((void**)&cnt, g_cnt);
    cudaGetSymbolAddress((void**)&Bhi, g_Bhi);

    // one-time resources (created on the uncaptured correctness call)
    static cudaStream_t s2 = nullptr;
    static cudaEvent_t evFork = nullptr, evJoin = nullptr;
    if (s2 == nullptr) {
        cudaStreamCreateWithFlags(&s2, cudaStreamNonBlocking);
        cudaEventCreateWithFlags(&evFork, cudaEventDisableTiming);
        cudaEventCreateWithFlags(&evJoin, cudaEventDisableTiming);
        cudaFuncSetAttribute(gemm_mma_kernel,
                             cudaFuncAttributeMaxDynamicSharedMemorySize,
                             SMEM_TOTAL);
    }

    // fork: sparsify runs on s2 concurrently with the GEMM chain
    cudaEventRecord(evFork, 0);
    cudaStreamWaitEvent(s2, evFork, 0);
    sparsify_kernel<<<M_N, 512, 0, s2>>>(graph, idx, cnt);
    cudaEventRecord(evJoin, s2);

    // main chain on the default stream
    convB_kernel<<<dim3(K_PAD / 32, HID / 32), dim3(32, 8)>>>(W0, Bhi);
    gemm_mma_kernel<<<dim3(HID / BN, M_N / BM), 512, SMEM_TOTAL>>>(node_features, Xh);
    fvec_kernel<<<M_N / 8, 256>>>(Xh, v0, v1, f0, f1);

    // join: attn needs both the GEMM chain and sparsify
    cudaStreamWaitEvent(0, evJoin, 0);
    attn_kernel<<<M_N, 256>>>(Xh, f0, f1, W1, idx, cnt, out);
}